// round 1
// baseline (speedup 1.0000x reference)
#include <cuda_runtime.h>
#include <cstdint>

#define CCH 256       // channels
#define TLEN 8192     // time
#define BSZ 4         // batch
#define TT 32         // time tile per block
#define NLAYER 10

// ---------------- device scratch (static, no allocation) ----------------
__device__ float g_wt[NLAYER * 3 * CCH * (2 * CCH)];   // [l][k][c][o]  (15.7 MB)
__device__ float g_wo[NLAYER * CCH * CCH];             // [l][c][o]     (2.6 MB)
__device__ float g_x[2 * (size_t)BSZ * CCH * TLEN];    // ping-pong x   (64 MB)

typedef unsigned long long u64;

__device__ __forceinline__ u64 pk2(float a, float b) {
    u64 r;
    asm("mov.b64 %0, {%1, %2};" : "=l"(r) : "f"(a), "f"(b));
    return r;
}
__device__ __forceinline__ u64 ffma2(u64 a, u64 b, u64 c) {
    u64 d;
    asm("fma.rn.f32x2 %0, %1, %2, %3;" : "=l"(d) : "l"(a), "l"(b), "l"(c));
    return d;
}
__device__ __forceinline__ float2 up2(u64 a) {
    float2 f;
    asm("mov.b64 {%0, %1}, %2;" : "=f"(f.x), "=f"(f.y) : "l"(a));
    return f;
}
__device__ __forceinline__ float sigf(float x) {
    return __fdividef(1.0f, 1.0f + __expf(-x));
}

// ---------------- weight transposes ----------------
// wconv: [L][2C][C][3]  ->  g_wt: [L][3][C][2C]
__global__ void transpose_conv_k(const float* __restrict__ w, float* __restrict__ wt) {
    const int total = NLAYER * (2 * CCH) * CCH * 3;
    for (int i = blockIdx.x * blockDim.x + threadIdx.x; i < total;
         i += gridDim.x * blockDim.x) {
        int k = i % 3;
        int c = (i / 3) % CCH;
        int o = (i / (3 * CCH)) % (2 * CCH);
        int l = i / (3 * CCH * 2 * CCH);
        wt[(((size_t)l * 3 + k) * CCH + c) * (2 * CCH) + o] = w[i];
    }
}
// wout: [L][C][C] (o,c) -> g_wo: [L][C][C] (c,o)
__global__ void transpose_out_k(const float* __restrict__ w, float* __restrict__ wt) {
    const int total = NLAYER * CCH * CCH;
    for (int i = blockIdx.x * blockDim.x + threadIdx.x; i < total;
         i += gridDim.x * blockDim.x) {
        int c = i % CCH;
        int o = (i / CCH) % CCH;
        int l = i / (CCH * CCH);
        wt[((size_t)l * CCH + c) * CCH + o] = w[i];
    }
}

// ---------------- fused layer kernel ----------------
// one block: batch b, time tile [t0, t0+32)
// phase1: load 3 shifted x tiles into smem
// phase2: z = conv (GEMM over k=3, c=256), packed f32x2 accum
// phase3: gate -> h; write skip; (last layer: write x_next = h + x)
// phase4: 1x1 out-proj + bias + residual -> x_next
__global__ __launch_bounds__(256, 1) void layer_kernel(
    const float* __restrict__ xin,
    float* __restrict__ xout,
    const float* __restrict__ wt,     // [3][C][2C]
    const float* __restrict__ bconv,  // [2C]
    const float* __restrict__ wot,    // [C][C]  (c-major)
    const float* __restrict__ bout,   // [C]
    float* __restrict__ skip,         // [B][C][T] slice of d_out
    int dil, int is_last)
{
    extern __shared__ float smem[];        // 3*C*TT = 24576 floats (96 KB)
    float* Xs  = smem;                     // Xs[k][c][tt] = smem[(k*C+c)*TT + tt]
    float* HsT = smem;                     // h, t-major [TT][257], overlaps Xs[0..1]

    const int tid = threadIdx.x;
    const int b   = blockIdx.y;
    const int t0  = blockIdx.x * TT;
    const float* xb = xin + (size_t)b * CCH * TLEN;

    // ---- phase 1: load shifted tiles (coalesced, 128B rows) ----
    for (int i = tid; i < 3 * CCH * TT; i += 256) {
        int k  = i >> 13;            // / (C*TT)
        int r  = i & 8191;
        int c  = r >> 5;
        int tt = r & 31;
        int ts = t0 + tt - dil * (2 - k);
        smem[i] = (ts >= 0) ? xb[c * TLEN + ts] : 0.0f;
    }
    __syncthreads();

    const int q     = tid & 63;
    const int ob    = q << 2;           // 4 consecutive output channels
    const int tbase = (tid >> 6) << 3;  // 8 consecutive t's

    // ---- phase 2: dilated conv GEMM ----
    u64 accT[16], accS[16];
    #pragma unroll
    for (int i = 0; i < 16; ++i) { accT[i] = 0ull; accS[i] = 0ull; }

    for (int c = 0; c < CCH; ++c) {
        #pragma unroll
        for (int k = 0; k < 3; ++k) {
            const float* xr = Xs + (((k << 8) + c) << 5) + tbase;
            u64 xv[4];
            xv[0] = *(const u64*)(xr);
            xv[1] = *(const u64*)(xr + 2);
            xv[2] = *(const u64*)(xr + 4);
            xv[3] = *(const u64*)(xr + 6);
            const float* wr = wt + ((size_t)(((k << 8) + c)) << 9) + ob;
            float4 wT = *(const float4*)wr;
            float4 wS = *(const float4*)(wr + CCH);
            float wTa[4] = {wT.x, wT.y, wT.z, wT.w};
            float wSa[4] = {wS.x, wS.y, wS.z, wS.w};
            #pragma unroll
            for (int oi = 0; oi < 4; ++oi) {
                u64 wp = pk2(wTa[oi], wTa[oi]);
                #pragma unroll
                for (int j = 0; j < 4; ++j)
                    accT[oi * 4 + j] = ffma2(wp, xv[j], accT[oi * 4 + j]);
                u64 ws = pk2(wSa[oi], wSa[oi]);
                #pragma unroll
                for (int j = 0; j < 4; ++j)
                    accS[oi * 4 + j] = ffma2(ws, xv[j], accS[oi * 4 + j]);
            }
        }
    }
    __syncthreads();   // everyone done reading Xs[0..1] before HsT overwrite

    // ---- phase 3: gate, skip write, (last layer residual) ----
    {
        float4 bT = *(const float4*)(bconv + ob);
        float4 bS = *(const float4*)(bconv + CCH + ob);
        float bTa[4] = {bT.x, bT.y, bT.z, bT.w};
        float bSa[4] = {bS.x, bS.y, bS.z, bS.w};
        #pragma unroll
        for (int oi = 0; oi < 4; ++oi) {
            int o = ob + oi;
            #pragma unroll
            for (int j = 0; j < 4; ++j) {
                int tt = tbase + 2 * j;
                float2 zt = up2(accT[oi * 4 + j]);
                float2 zs = up2(accS[oi * 4 + j]);
                float h0 = tanhf(zt.x + bTa[oi]) * sigf(zs.x + bSa[oi]);
                float h1 = tanhf(zt.y + bTa[oi]) * sigf(zs.y + bSa[oi]);
                float2 hv = make_float2(h0, h1);
                *(float2*)(skip + ((size_t)b * CCH + o) * TLEN + t0 + tt) = hv;
                if (is_last) {
                    const float2 xr = *(const float2*)(Xs + 2 * CCH * TT + o * TT + tt);
                    float2 ov = make_float2(h0 + xr.x, h1 + xr.y);
                    *(float2*)(xout + ((size_t)b * CCH + o) * TLEN + t0 + tt) = ov;
                } else {
                    HsT[tt * 257 + o]       = h0;
                    HsT[(tt + 1) * 257 + o] = h1;
                }
            }
        }
    }
    if (is_last) return;
    __syncthreads();

    // ---- phase 4: 1x1 out-proj + bias + residual ----
    {
        u64 acc[16];
        #pragma unroll
        for (int i = 0; i < 16; ++i) acc[i] = 0ull;

        for (int c = 0; c < CCH; ++c) {
            u64 hv[4];
            #pragma unroll
            for (int j = 0; j < 4; ++j) {
                int tt = tbase + 2 * j;
                hv[j] = pk2(HsT[tt * 257 + c], HsT[(tt + 1) * 257 + c]);
            }
            const float4 w4 = *(const float4*)(wot + (c << 8) + ob);
            float wa[4] = {w4.x, w4.y, w4.z, w4.w};
            #pragma unroll
            for (int oi = 0; oi < 4; ++oi) {
                u64 wp = pk2(wa[oi], wa[oi]);
                #pragma unroll
                for (int j = 0; j < 4; ++j)
                    acc[oi * 4 + j] = ffma2(wp, hv[j], acc[oi * 4 + j]);
            }
        }

        float4 bo = *(const float4*)(bout + ob);
        float boa[4] = {bo.x, bo.y, bo.z, bo.w};
        #pragma unroll
        for (int oi = 0; oi < 4; ++oi) {
            int o = ob + oi;
            #pragma unroll
            for (int j = 0; j < 4; ++j) {
                int tt = tbase + 2 * j;
                float2 v = up2(acc[oi * 4 + j]);
                const float2 xr = *(const float2*)(Xs + 2 * CCH * TT + o * TT + tt);
                v.x += boa[oi] + xr.x;
                v.y += boa[oi] + xr.y;
                *(float2*)(xout + ((size_t)b * CCH + o) * TLEN + t0 + tt) = v;
            }
        }
    }
}

// ---------------- host launcher ----------------
extern "C" void kernel_launch(void* const* d_in, const int* in_sizes, int n_in,
                              void* d_out, int out_size) {
    const float* input = (const float*)d_in[0];
    const float* wconv = (const float*)d_in[1];
    const float* bconv = (const float*)d_in[2];
    const float* wout  = (const float*)d_in[3];
    const float* bout  = (const float*)d_in[4];
    float* out = (float*)d_out;

    float *wt_d = nullptr, *wo_d = nullptr, *x_d = nullptr;
    cudaGetSymbolAddress((void**)&wt_d, g_wt);
    cudaGetSymbolAddress((void**)&wo_d, g_wo);
    cudaGetSymbolAddress((void**)&x_d,  g_x);

    cudaFuncSetAttribute(layer_kernel,
                         cudaFuncAttributeMaxDynamicSharedMemorySize, 98304);

    transpose_conv_k<<<2048, 256>>>(wconv, wt_d);
    transpose_out_k<<<512, 256>>>(wout, wo_d);

    const size_t XE = (size_t)BSZ * CCH * TLEN;   // 8388608
    const int DIL[NLAYER] = {1, 2, 4, 8, 16, 32, 64, 128, 256, 512};

    const float* xin = input;
    for (int l = 0; l < NLAYER; ++l) {
        float* xo   = (l == NLAYER - 1) ? out : (x_d + (size_t)(l & 1) * XE);
        float* skip = out + XE + (size_t)l * XE;
        dim3 grid(TLEN / TT, BSZ);
        layer_kernel<<<grid, 256, 98304>>>(
            xin, xo,
            wt_d + (size_t)l * 3 * CCH * 2 * CCH,
            bconv + l * 2 * CCH,
            wo_d + (size_t)l * CCH * CCH,
            bout + l * CCH,
            skip, DIL[l], (l == NLAYER - 1) ? 1 : 0);
        xin = xo;
    }
    (void)in_sizes; (void)n_in; (void)out_size;
}